// round 10
// baseline (speedup 1.0000x reference)
#include <cuda_runtime.h>

#define HH 512
#define WW 512
#define BB 2
#define NP 256          // uint32 pixel-pairs per row
#define CH 8            // radii per chunk

// Packed row-pass result, one uint16 per pixel:
//   bit15 = mask (1 = fg), bits[0:15) = row distance to nearest OPPOSITE-class
//   pixel (0x7fff sentinel = none in this row; its squared value can never
//   beat any real candidate). 1 MB, L2-resident.
__device__ unsigned short g_pack16[BB * HH * WW];

// ---------------------------------------------------------------------------
// Kernel A: row pass via 512-bit row bitmask + ffs/clz word scans (best
// measured form). 1 row per block, 1 pixel per thread.
// ---------------------------------------------------------------------------
__global__ void __launch_bounds__(WW) row_pass(const float* __restrict__ gt) {
    const int b = blockIdx.x >> 9;          // blockIdx.x = b*512 + y
    const int y = blockIdx.x & 511;
    const int x = threadIdx.x;

    __shared__ unsigned int sw[WW / 32];    // 16 words = 512-bit row mask

    const float v = gt[((size_t)b * HH + y) * WW + x];
    const unsigned int m = (v == 1.0f) ? 1u : 0u;
    const unsigned int bits = __ballot_sync(0xFFFFFFFFu, m != 0u);
    if ((x & 31) == 0) sw[x >> 5] = bits;
    __syncthreads();

    const unsigned int xorm = m ? 0xFFFFFFFFu : 0u;  // opp(word) = word ^ xorm
    const int w0 = x >> 5, off = x & 31;
    const unsigned int cur = sw[w0] ^ xorm;

    int right = 0x7fff;
    {
        const unsigned int hi = cur & (0xFFFFFFFEu << off);
        if (hi) {
            right = (__ffs(hi) - 1) - off;
        } else {
            #pragma unroll 1
            for (int w = w0 + 1; w < WW / 32; ++w) {
                const unsigned int q = sw[w] ^ xorm;
                if (q) { right = (w << 5) + (__ffs(q) - 1) - x; break; }
            }
        }
    }
    int left = 0x7fff;
    {
        const unsigned int lo = cur & ((1u << off) - 1u);
        if (lo) {
            left = off - (31 - __clz(lo));
        } else {
            #pragma unroll 1
            for (int w = w0 - 1; w >= 0; --w) {
                const unsigned int q = sw[w] ^ xorm;
                if (q) { left = x - ((w << 5) + (31 - __clz(q))); break; }
            }
        }
    }

    const unsigned int d = (unsigned int)min(min(left, right), 0x7fff);
    g_pack16[((size_t)b * HH + y) * WW + x] = (unsigned short)(d | (m << 15));
}

// ---------------------------------------------------------------------------
// Kernel B: column pass, CHUNKED adaptive scan.
// Radii processed in chunks of CH=8: all 16 clamped branch-free loads of a
// chunk are independent (one L2 round-trip per chunk instead of per radius),
// then the exact-window break (rbase^2 >= best) is tested once per chunk.
// Exactness: extra candidates are always valid upper bounds of the min, and
// the chunk break only stops once the remaining radii provably cannot help.
// Opposite plane only; 2 px/thread per uint32; fused sqrt epilogue.
// ---------------------------------------------------------------------------
__global__ void __launch_bounds__(256) col_pass(float* __restrict__ out) {
    const int b = blockIdx.x >> 9;           // blockIdx.x = b*512 + i
    const int i = blockIdx.x & 511;
    const int t = threadIdx.x;

    const unsigned int* __restrict__ col =
        reinterpret_cast<const unsigned int*>(g_pack16) +
        (size_t)b * HH * NP + t;

    const unsigned int u = __ldcg(&col[i * NP]);
    const unsigned int mA = (u >> 15) & 1u;
    const unsigned int mB = (u >> 31) & 1u;
    const int roA = (int)(u & 0x7fffu);
    const int roB = (int)((u >> 16) & 0x7fffu);
    float bestA = (float)(roA * roA);
    float bestB = (float)(roB * roB);

    #pragma unroll 1
    for (int rbase = 1; rbase < HH; rbase += CH) {
        const float rb2 = (float)(rbase * rbase);
        if (rb2 >= bestA && rb2 >= bestB) break;

        unsigned int qu[CH], qd[CH];
        #pragma unroll
        for (int k = 0; k < CH; ++k) {
            const int r = rbase + k;
            qu[k] = __ldcg(&col[max(i - r, 0) * NP]);
            qd[k] = __ldcg(&col[min(i + r, HH - 1) * NP]);
        }

        #pragma unroll
        for (int k = 0; k < CH; ++k) {
            const int r = rbase + k;
            const float rr = (float)(r * r);
            const float pu = (i - r >= 0) ? rr : 1e12f;
            const float pd = (i + r < HH) ? rr : 1e12f;

            const unsigned int a = qu[k];
            const int ra = (int)(a & 0x7fffu), rb = (int)((a >> 16) & 0x7fffu);
            bestA = fminf(bestA, ((((a >> 15) & 1u) != mA) ? 0.0f : (float)(ra * ra)) + pu);
            bestB = fminf(bestB, ((((a >> 31) & 1u) != mB) ? 0.0f : (float)(rb * rb)) + pu);

            const unsigned int c = qd[k];
            const int rc = (int)(c & 0x7fffu), rd = (int)((c >> 16) & 0x7fffu);
            bestA = fminf(bestA, ((((c >> 15) & 1u) != mA) ? 0.0f : (float)(rc * rc)) + pd);
            bestB = fminf(bestB, ((((c >> 31) & 1u) != mB) ? 0.0f : (float)(rd * rd)) + pd);
        }
    }

    float2 o;
    o.x = (mA ? -1.0f : 1.0f) * sqrtf(bestA);
    o.y = (mB ? -1.0f : 1.0f) * sqrtf(bestB);
    reinterpret_cast<float2*>(out + ((size_t)b * HH + i) * WW)[t] = o;
}

extern "C" void kernel_launch(void* const* d_in, const int* in_sizes, int n_in,
                              void* d_out, int out_size) {
    const float* gt = (const float*)d_in[0];
    float* out = (float*)d_out;
    (void)in_sizes; (void)n_in; (void)out_size;

    row_pass<<<BB * HH, WW>>>(gt);
    col_pass<<<BB * HH, 256>>>(out);
}

// round 11
// speedup vs baseline: 1.3000x; 1.3000x over previous
#include <cuda_runtime.h>

#define HH 512
#define WW 512
#define BB 2
#define NP 256          // uint32 pixel-pairs per row
#define PINF 1e12f      // disables OOB candidates; never beats any real one

// Packed row-pass result, one uint16 per pixel:
//   bit15 = mask (1 = fg), bits[0:15) = row distance to nearest OPPOSITE-class
//   pixel (0x7fff sentinel = none in this row; its squared value ~1.07e9 can
//   never beat any real candidate <= 511^2 + 511^2). 1 MB, L2-resident.
__device__ unsigned short g_pack16[BB * HH * WW];

// ---------------------------------------------------------------------------
// Kernel A: row pass via 512-bit row bitmask + ffs/clz word scans (best
// measured form, R4). 1 row per block, 1 pixel per thread.
// ---------------------------------------------------------------------------
__global__ void __launch_bounds__(WW) row_pass(const float* __restrict__ gt) {
    const int b = blockIdx.x >> 9;          // blockIdx.x = b*512 + y
    const int y = blockIdx.x & 511;
    const int x = threadIdx.x;

    __shared__ unsigned int sw[WW / 32];    // 16 words = 512-bit row mask

    const float v = gt[((size_t)b * HH + y) * WW + x];
    const unsigned int m = (v == 1.0f) ? 1u : 0u;
    const unsigned int bits = __ballot_sync(0xFFFFFFFFu, m != 0u);
    if ((x & 31) == 0) sw[x >> 5] = bits;
    __syncthreads();

    const unsigned int xorm = m ? 0xFFFFFFFFu : 0u;  // opp(word) = word ^ xorm
    const int w0 = x >> 5, off = x & 31;
    const unsigned int cur = sw[w0] ^ xorm;

    int right = 0x7fff;
    {
        const unsigned int hi = cur & (0xFFFFFFFEu << off);
        if (hi) {
            right = (__ffs(hi) - 1) - off;
        } else {
            #pragma unroll 1
            for (int w = w0 + 1; w < WW / 32; ++w) {
                const unsigned int q = sw[w] ^ xorm;
                if (q) { right = (w << 5) + (__ffs(q) - 1) - x; break; }
            }
        }
    }
    int left = 0x7fff;
    {
        const unsigned int lo = cur & ((1u << off) - 1u);
        if (lo) {
            left = off - (31 - __clz(lo));
        } else {
            #pragma unroll 1
            for (int w = w0 - 1; w >= 0; --w) {
                const unsigned int q = sw[w] ^ xorm;
                if (q) { left = x - ((w << 5) + (31 - __clz(q))); break; }
            }
        }
    }

    const unsigned int d = (unsigned int)min(min(left, right), 0x7fff);
    g_pack16[((size_t)b * HH + y) * WW + x] = (unsigned short)(d | (m << 15));
}

// Branchless fold of one neighbor word into the running mins.
__device__ __forceinline__ void fold(unsigned int q, unsigned int mA,
                                     unsigned int mB, float pen,
                                     float& bestA, float& bestB) {
    const int ra = (int)(q & 0x7fffu);
    const int rb = (int)((q >> 16) & 0x7fffu);
    const float fa = (((q >> 15) & 1u) != mA) ? 0.0f : (float)(ra * ra);
    const float fb = (((q >> 31) & 1u) != mB) ? 0.0f : (float)(rb * rb);
    bestA = fminf(bestA, fa + pen);
    bestB = fminf(bestB, fb + pen);
}

// ---------------------------------------------------------------------------
// Kernel B: column pass, PEELED adaptive scan.
// The center and the r=1,2 neighbor rows are loaded unconditionally up front
// (5 address-independent loads -> ONE L2 round-trip) and folded branchlessly.
// ~97% of pixels then satisfy 9 >= best and never enter the loop; the rest
// continue with the lean per-radius break-scan from r=3 (exact: stop only
// when r^2 >= best, since any j with (i-j)^2 >= best cannot improve the min;
// extra candidates are always valid upper bounds).
// Opposite plane only; 2 px/thread per uint32; fused sqrt epilogue.
// ---------------------------------------------------------------------------
__global__ void __launch_bounds__(256) col_pass(float* __restrict__ out) {
    const int b = blockIdx.x >> 9;           // blockIdx.x = b*512 + i
    const int i = blockIdx.x & 511;
    const int t = threadIdx.x;

    const unsigned int* __restrict__ col =
        reinterpret_cast<const unsigned int*>(g_pack16) +
        (size_t)b * HH * NP + t;

    // 5 independent loads: center, i-1, i+1, i-2, i+2 (clamped).
    const unsigned int u  = col[i * NP];
    const unsigned int q1u = col[max(i - 1, 0) * NP];
    const unsigned int q1d = col[min(i + 1, HH - 1) * NP];
    const unsigned int q2u = col[max(i - 2, 0) * NP];
    const unsigned int q2d = col[min(i + 2, HH - 1) * NP];

    const unsigned int mA = (u >> 15) & 1u;
    const unsigned int mB = (u >> 31) & 1u;
    const int roA = (int)(u & 0x7fffu);
    const int roB = (int)((u >> 16) & 0x7fffu);
    float bestA = (float)(roA * roA);
    float bestB = (float)(roB * roB);

    fold(q1u, mA, mB, (i - 1 >= 0) ? 1.0f : PINF, bestA, bestB);
    fold(q1d, mA, mB, (i + 1 < HH) ? 1.0f : PINF, bestA, bestB);
    fold(q2u, mA, mB, (i - 2 >= 0) ? 4.0f : PINF, bestA, bestB);
    fold(q2d, mA, mB, (i + 2 < HH) ? 4.0f : PINF, bestA, bestB);

    // Tail loop for the rare pixels with best > 9.
    #pragma unroll 1
    for (int r = 3; r < HH; ++r) {
        const float rr = (float)(r * r);
        if (rr >= bestA && rr >= bestB) break;
        const int up = i - r, dn = i + r;
        if (up >= 0)  fold(col[up * NP], mA, mB, rr, bestA, bestB);
        if (dn < HH)  fold(col[dn * NP], mA, mB, rr, bestA, bestB);
    }

    float2 o;
    o.x = (mA ? -1.0f : 1.0f) * sqrtf(bestA);
    o.y = (mB ? -1.0f : 1.0f) * sqrtf(bestB);
    reinterpret_cast<float2*>(out + ((size_t)b * HH + i) * WW)[t] = o;
}

extern "C" void kernel_launch(void* const* d_in, const int* in_sizes, int n_in,
                              void* d_out, int out_size) {
    const float* gt = (const float*)d_in[0];
    float* out = (float*)d_out;
    (void)in_sizes; (void)n_in; (void)out_size;

    row_pass<<<BB * HH, WW>>>(gt);
    col_pass<<<BB * HH, 256>>>(out);
}

// round 12
// speedup vs baseline: 1.4198x; 1.0922x over previous
#include <cuda_runtime.h>

#define HH 512
#define WW 512
#define BB 2
#define NP 256          // uint32 pixel-pairs per row
#define PINF 1e12f      // disables OOB candidates; never beats any real one

// Packed row-pass result, one uint16 per pixel:
//   bit15 = mask (1 = fg), bits[0:15) = row distance to nearest OPPOSITE-class
//   pixel (0x7fff sentinel = none in this row; its squared value ~1.07e9 can
//   never beat any real candidate <= 511^2 + 511^2). 1 MB, L2-resident.
__device__ unsigned short g_pack16[BB * HH * WW];

// ---------------------------------------------------------------------------
// Kernel A: row pass via 512-bit row bitmask + ffs/clz word scans (best
// measured form). 1 row per block, 1 pixel per thread.
// ---------------------------------------------------------------------------
__global__ void __launch_bounds__(WW) row_pass(const float* __restrict__ gt) {
    const int b = blockIdx.x >> 9;          // blockIdx.x = b*512 + y
    const int y = blockIdx.x & 511;
    const int x = threadIdx.x;

    __shared__ unsigned int sw[WW / 32];    // 16 words = 512-bit row mask

    const float v = gt[((size_t)b * HH + y) * WW + x];
    const unsigned int m = (v == 1.0f) ? 1u : 0u;
    const unsigned int bits = __ballot_sync(0xFFFFFFFFu, m != 0u);
    if ((x & 31) == 0) sw[x >> 5] = bits;
    __syncthreads();

    const unsigned int xorm = m ? 0xFFFFFFFFu : 0u;  // opp(word) = word ^ xorm
    const int w0 = x >> 5, off = x & 31;
    const unsigned int cur = sw[w0] ^ xorm;

    int right = 0x7fff;
    {
        const unsigned int hi = cur & (0xFFFFFFFEu << off);
        if (hi) {
            right = (__ffs(hi) - 1) - off;
        } else {
            #pragma unroll 1
            for (int w = w0 + 1; w < WW / 32; ++w) {
                const unsigned int q = sw[w] ^ xorm;
                if (q) { right = (w << 5) + (__ffs(q) - 1) - x; break; }
            }
        }
    }
    int left = 0x7fff;
    {
        const unsigned int lo = cur & ((1u << off) - 1u);
        if (lo) {
            left = off - (31 - __clz(lo));
        } else {
            #pragma unroll 1
            for (int w = w0 - 1; w >= 0; --w) {
                const unsigned int q = sw[w] ^ xorm;
                if (q) { left = x - ((w << 5) + (31 - __clz(q))); break; }
            }
        }
    }

    const unsigned int d = (unsigned int)min(min(left, right), 0x7fff);
    g_pack16[((size_t)b * HH + y) * WW + x] = (unsigned short)(d | (m << 15));
}

// Branchless fold of one neighbor word into the running mins.
__device__ __forceinline__ void fold(unsigned int q, unsigned int mA,
                                     unsigned int mB, float pen,
                                     float& bestA, float& bestB) {
    const int ra = (int)(q & 0x7fffu);
    const int rb = (int)((q >> 16) & 0x7fffu);
    const float fa = (((q >> 15) & 1u) != mA) ? 0.0f : (float)(ra * ra);
    const float fb = (((q >> 31) & 1u) != mB) ? 0.0f : (float)(rb * rb);
    bestA = fminf(bestA, fa + pen);
    bestB = fminf(bestB, fb + pen);
}

// One independent-load chunk of radii [rlo, rlo+N): 2N clamped loads issued
// back-to-back (single L2 round-trip), folded branchlessly.
template <int N>
__device__ __forceinline__ void chunk(const unsigned int* __restrict__ col,
                                      int i, int rlo, unsigned int mA,
                                      unsigned int mB, float& bestA,
                                      float& bestB) {
    unsigned int qu[N], qd[N];
    #pragma unroll
    for (int k = 0; k < N; ++k) {
        const int r = rlo + k;
        qu[k] = col[max(i - r, 0) * NP];
        qd[k] = col[min(i + r, HH - 1) * NP];
    }
    #pragma unroll
    for (int k = 0; k < N; ++k) {
        const int r = rlo + k;
        const float rr = (float)(r * r);
        fold(qu[k], mA, mB, (i - r >= 0) ? rr : PINF, bestA, bestB);
        fold(qd[k], mA, mB, (i + r < HH) ? rr : PINF, bestA, bestB);
    }
}

// ---------------------------------------------------------------------------
// Kernel B: column pass, PEEL + GEOMETRIC CHUNKS.
//   peel r<=2 (5 loads, 1 L2 round-trip, unconditional)      ~97% done
//   chunk r=3..6  (8 loads, 1 RT)  if break not yet satisfied ~40% of warps
//   chunk r=7..14 (16 loads, 1 RT) if still unsatisfied        ~2% of warps
//   per-radius loop r>=15 for the vanishing residue.
// Exact: each break tests rbase^2 >= best (the exact window condition);
// extra candidates are always valid upper bounds of the min.
// Opposite plane only; 2 px/thread per uint32; fused sqrt epilogue.
// ---------------------------------------------------------------------------
__global__ void __launch_bounds__(256) col_pass(float* __restrict__ out) {
    const int b = blockIdx.x >> 9;           // blockIdx.x = b*512 + i
    const int i = blockIdx.x & 511;
    const int t = threadIdx.x;

    const unsigned int* __restrict__ col =
        reinterpret_cast<const unsigned int*>(g_pack16) +
        (size_t)b * HH * NP + t;

    // Peel: center + r=1,2 (5 independent loads).
    const unsigned int u   = col[i * NP];
    const unsigned int q1u = col[max(i - 1, 0) * NP];
    const unsigned int q1d = col[min(i + 1, HH - 1) * NP];
    const unsigned int q2u = col[max(i - 2, 0) * NP];
    const unsigned int q2d = col[min(i + 2, HH - 1) * NP];

    const unsigned int mA = (u >> 15) & 1u;
    const unsigned int mB = (u >> 31) & 1u;
    const int roA = (int)(u & 0x7fffu);
    const int roB = (int)((u >> 16) & 0x7fffu);
    float bestA = (float)(roA * roA);
    float bestB = (float)(roB * roB);

    fold(q1u, mA, mB, (i - 1 >= 0) ? 1.0f : PINF, bestA, bestB);
    fold(q1d, mA, mB, (i + 1 < HH) ? 1.0f : PINF, bestA, bestB);
    fold(q2u, mA, mB, (i - 2 >= 0) ? 4.0f : PINF, bestA, bestB);
    fold(q2d, mA, mB, (i + 2 < HH) ? 4.0f : PINF, bestA, bestB);

    // Chunk r = 3..6 (break iff 9 >= best for both planes).
    if (9.0f < bestA || 9.0f < bestB) {
        chunk<4>(col, i, 3, mA, mB, bestA, bestB);

        // Chunk r = 7..14.
        if (49.0f < bestA || 49.0f < bestB) {
            chunk<8>(col, i, 7, mA, mB, bestA, bestB);

            // Residue: per-radius exact scan from r = 15.
            #pragma unroll 1
            for (int r = 15; r < HH; ++r) {
                const float rr = (float)(r * r);
                if (rr >= bestA && rr >= bestB) break;
                const int up = i - r, dn = i + r;
                if (up >= 0)  fold(col[up * NP], mA, mB, rr, bestA, bestB);
                if (dn < HH)  fold(col[dn * NP], mA, mB, rr, bestA, bestB);
            }
        }
    }

    float2 o;
    o.x = (mA ? -1.0f : 1.0f) * sqrtf(bestA);
    o.y = (mB ? -1.0f : 1.0f) * sqrtf(bestB);
    reinterpret_cast<float2*>(out + ((size_t)b * HH + i) * WW)[t] = o;
}

extern "C" void kernel_launch(void* const* d_in, const int* in_sizes, int n_in,
                              void* d_out, int out_size) {
    const float* gt = (const float*)d_in[0];
    float* out = (float*)d_out;
    (void)in_sizes; (void)n_in; (void)out_size;

    row_pass<<<BB * HH, WW>>>(gt);
    col_pass<<<BB * HH, 256>>>(out);
}

// round 13
// speedup vs baseline: 1.4345x; 1.0103x over previous
#include <cuda_runtime.h>

#define HH 512
#define WW 512
#define BB 2
#define NPG 128         // uint2 pixel-groups (4 px) per row
#define PINF 1e12f

// Packed row-pass result, one uint16 per pixel:
//   bit15 = mask (1 = fg), bits[0:15) = row distance to nearest OPPOSITE-class
//   pixel (0x7fff sentinel = none in this row; its squared value ~1.07e9 can
//   never beat any real candidate). 1 MB, L2-resident.
__device__ unsigned short g_pack16[BB * HH * WW];

// ---------------------------------------------------------------------------
// Kernel A: row pass, 4 pixels/thread via float4. 4 rows per block
// (512 thr = 4 x 128). Row bitmask built with shfl_xor nibble packing,
// nearest-opposite-bit via ffs/clz word scans (pure ALU, no latency chain).
// ---------------------------------------------------------------------------
__global__ void __launch_bounds__(512) row_pass(const float* __restrict__ gt) {
    const int g = blockIdx.x * 4 + (threadIdx.x >> 7);   // global row id
    const int tx = threadIdx.x & 127;                    // float4 index in row
    const int rl = threadIdx.x >> 7;

    __shared__ unsigned int sw[4][WW / 32];

    const float4 v = reinterpret_cast<const float4*>(gt + (size_t)g * WW)[tx];
    const unsigned int nib = ((v.x == 1.0f) ? 1u : 0u)
                           | ((v.y == 1.0f) ? 2u : 0u)
                           | ((v.z == 1.0f) ? 4u : 0u)
                           | ((v.w == 1.0f) ? 8u : 0u);

    // Pack nibbles into 32-bit words within 8-lane groups.
    unsigned int pv = nib << (4 * (tx & 7));
    pv |= __shfl_xor_sync(0xFFFFFFFFu, pv, 1);
    pv |= __shfl_xor_sync(0xFFFFFFFFu, pv, 2);
    pv |= __shfl_xor_sync(0xFFFFFFFFu, pv, 4);
    if ((tx & 7) == 0) sw[rl][tx >> 3] = pv;   // word index = tx/8
    __syncthreads();

    const int w0 = tx >> 3;                    // all 4 px share this word
    unsigned long long res = 0ull;

    #pragma unroll
    for (int k = 0; k < 4; ++k) {
        const int x = tx * 4 + k;
        const unsigned int m = (nib >> k) & 1u;
        const unsigned int xorm = m ? 0xFFFFFFFFu : 0u;
        const int off = x & 31;
        const unsigned int cur = sw[rl][w0] ^ xorm;

        int right = 0x7fff;
        {
            const unsigned int hi = cur & (0xFFFFFFFEu << off);
            if (hi) {
                right = (__ffs(hi) - 1) - off;
            } else {
                #pragma unroll 1
                for (int w = w0 + 1; w < WW / 32; ++w) {
                    const unsigned int q = sw[rl][w] ^ xorm;
                    if (q) { right = (w << 5) + (__ffs(q) - 1) - x; break; }
                }
            }
        }
        int left = 0x7fff;
        {
            const unsigned int lo = cur & ((1u << off) - 1u);
            if (lo) {
                left = off - (31 - __clz(lo));
            } else {
                #pragma unroll 1
                for (int w = w0 - 1; w >= 0; --w) {
                    const unsigned int q = sw[rl][w] ^ xorm;
                    if (q) { left = x - ((w << 5) + (31 - __clz(q))); break; }
                }
            }
        }

        const unsigned int d = (unsigned int)min(min(left, right), 0x7fff);
        res |= (unsigned long long)(d | (m << 15)) << (16 * k);
    }

    reinterpret_cast<unsigned long long*>(g_pack16 + (size_t)g * WW)[tx] = res;
}

// Branchless fold of one uint2 (4 pixels) into the running mins.
__device__ __forceinline__ void fold4(uint2 q, const unsigned int* m,
                                      float pen, float* best) {
    #pragma unroll
    for (int p = 0; p < 4; ++p) {
        const unsigned int word = (p < 2) ? q.x : q.y;
        const int sh = (p & 1) * 16;
        const int ro = (int)((word >> sh) & 0x7fffu);
        const unsigned int mb = (word >> (sh + 15)) & 1u;
        const float f = (mb != m[p]) ? 0.0f : (float)(ro * ro);
        best[p] = fminf(best[p], f + pen);
    }
}

template <int N>
__device__ __forceinline__ void chunk4(const uint2* __restrict__ col, int i,
                                       int rlo, const unsigned int* m,
                                       float* best) {
    uint2 qu[N], qd[N];
    #pragma unroll
    for (int k = 0; k < N; ++k) {
        const int r = rlo + k;
        qu[k] = col[max(i - r, 0) * NPG];
        qd[k] = col[min(i + r, HH - 1) * NPG];
    }
    #pragma unroll
    for (int k = 0; k < N; ++k) {
        const int r = rlo + k;
        const float rr = (float)(r * r);
        fold4(qu[k], m, (i - r >= 0) ? rr : PINF, best);
        fold4(qd[k], m, (i + r < HH) ? rr : PINF, best);
    }
}

// ---------------------------------------------------------------------------
// Kernel B: column pass, 4 pixels/thread via uint2. One scan per thread.
//   peel r<=2 (5 loads, 1 L2 round-trip)           -> most threads done
//   chunk r=3..6, chunk r=7..14 (1 RT each)        -> shrinking tail
//   per-radius residue r>=15.
// Exact: breaks test rbase^2 >= best (exact window); extra candidates are
// valid upper bounds. Fused epilogue out = (m ? -1 : +1)*sqrt(best), float4.
// ---------------------------------------------------------------------------
__global__ void __launch_bounds__(256) col_pass(float* __restrict__ out) {
    const int L = blockIdx.x * 256 + threadIdx.x;  // linear work id
    const int w = L >> 7;                          // row-work: b*512 + i
    const int gx = L & 127;                        // uint2 group in row
    const int b = w >> 9;
    const int i = w & 511;

    const uint2* __restrict__ col =
        reinterpret_cast<const uint2*>(g_pack16) + (size_t)b * HH * NPG + gx;

    const uint2 u   = col[i * NPG];
    const uint2 q1u = col[max(i - 1, 0) * NPG];
    const uint2 q1d = col[min(i + 1, HH - 1) * NPG];
    const uint2 q2u = col[max(i - 2, 0) * NPG];
    const uint2 q2d = col[min(i + 2, HH - 1) * NPG];

    unsigned int m[4];
    float best[4];
    #pragma unroll
    for (int p = 0; p < 4; ++p) {
        const unsigned int word = (p < 2) ? u.x : u.y;
        const int sh = (p & 1) * 16;
        m[p] = (word >> (sh + 15)) & 1u;
        const int ro = (int)((word >> sh) & 0x7fffu);
        best[p] = (float)(ro * ro);
    }

    fold4(q1u, m, (i - 1 >= 0) ? 1.0f : PINF, best);
    fold4(q1d, m, (i + 1 < HH) ? 1.0f : PINF, best);
    fold4(q2u, m, (i - 2 >= 0) ? 4.0f : PINF, best);
    fold4(q2d, m, (i + 2 < HH) ? 4.0f : PINF, best);

    float bmax = fmaxf(fmaxf(best[0], best[1]), fmaxf(best[2], best[3]));
    if (bmax > 9.0f) {
        chunk4<4>(col, i, 3, m, best);
        bmax = fmaxf(fmaxf(best[0], best[1]), fmaxf(best[2], best[3]));
        if (bmax > 49.0f) {
            chunk4<8>(col, i, 7, m, best);
            #pragma unroll 1
            for (int r = 15; r < HH; ++r) {
                const float rr = (float)(r * r);
                bmax = fmaxf(fmaxf(best[0], best[1]), fmaxf(best[2], best[3]));
                if (rr >= bmax) break;
                const int up = i - r, dn = i + r;
                if (up >= 0)  fold4(col[up * NPG], m, rr, best);
                if (dn < HH)  fold4(col[dn * NPG], m, rr, best);
            }
        }
    }

    float4 o;
    o.x = (m[0] ? -1.0f : 1.0f) * sqrtf(best[0]);
    o.y = (m[1] ? -1.0f : 1.0f) * sqrtf(best[1]);
    o.z = (m[2] ? -1.0f : 1.0f) * sqrtf(best[2]);
    o.w = (m[3] ? -1.0f : 1.0f) * sqrtf(best[3]);
    reinterpret_cast<float4*>(out)[(size_t)w * NPG + gx] = o;
}

extern "C" void kernel_launch(void* const* d_in, const int* in_sizes, int n_in,
                              void* d_out, int out_size) {
    const float* gt = (const float*)d_in[0];
    float* out = (float*)d_out;
    (void)in_sizes; (void)n_in; (void)out_size;

    row_pass<<<BB * HH / 4, 512>>>(gt);
    col_pass<<<BB * HH * NPG / 256, 256>>>(out);
}